// round 3
// baseline (speedup 1.0000x reference)
#include <cuda_runtime.h>
#include <cuda_bf16.h>

// Problem constants
#define NN 100000
#define EE 1600000
#define FD 128
#define NG 128
#define OD 16

// Scratch (device globals — no allocs allowed)
__device__ float g_deg[NN];             // degree, then dinv after k_dinv
__device__ float g_bufA[(long)NN * FD]; // GEMM output (scaled by dinv[src])
__device__ float g_bufB[(long)NN * FD]; // aggregation target / layer output
__device__ float g_pool[NG * FD];
__device__ float g_cnt[NG];

// ---------------- degree ----------------
__global__ void k_deg_init(int n) {
    int i = blockIdx.x * blockDim.x + threadIdx.x;
    if (i < n) g_deg[i] = 1.0f;  // self-loop
}

__global__ void k_deg_count(const int* __restrict__ ei, int e) {
    int stride = gridDim.x * blockDim.x;
    for (int i = blockIdx.x * blockDim.x + threadIdx.x; i < e; i += stride) {
        int d = ei[e + i];  // dst row
        if ((unsigned)d < NN) atomicAdd(&g_deg[d], 1.0f);
    }
}

__global__ void k_dinv(int n) {
    int i = blockIdx.x * blockDim.x + threadIdx.x;
    if (i < n) g_deg[i] = rsqrtf(g_deg[i]);
}

// ---------------- GEMM: g_bufA[m][:] = (A[m][:] @ W) * dinv[m] ----------------
// A: [M,128] (x input if src_sel==0, g_bufB if src_sel==1), W: [128,128] row-major.
// 128x128 block tile, KT=16, 256 threads, 8x8 micro-tile.
__global__ __launch_bounds__(256) void k_gemm_dinv(
    const float* __restrict__ Ax, const float* __restrict__ W,
    int M, int src_sel)
{
    const float* __restrict__ A = src_sel ? (const float*)g_bufB : Ax;
    __shared__ float As[16][128];
    __shared__ float Ws[16][128];
    const int tid = threadIdx.x;
    const int row0 = blockIdx.x * 128;
    const int ty = tid >> 4, tx = tid & 15;
    const int m0 = ty * 8, n0 = tx * 8;
    const int lm = tid & 127;

    float acc[8][8];
#pragma unroll
    for (int i = 0; i < 8; i++)
#pragma unroll
        for (int j = 0; j < 8; j++) acc[i][j] = 0.f;

    for (int kt = 0; kt < 128; kt += 16) {
        // Load A tile (transposed into As[k][m])
        int mA = row0 + lm;
#pragma unroll
        for (int i = 0; i < 2; i++) {
            int q = ((tid >> 7) << 1) + i;  // quad 0..3 -> k offset q*4
            float4 v = make_float4(0.f, 0.f, 0.f, 0.f);
            if (mA < M) v = *(const float4*)(A + (long)mA * 128 + kt + q * 4);
            As[q * 4 + 0][lm] = v.x;
            As[q * 4 + 1][lm] = v.y;
            As[q * 4 + 2][lm] = v.z;
            As[q * 4 + 3][lm] = v.w;
        }
        // Load W tile
#pragma unroll
        for (int i = 0; i < 2; i++) {
            int idx = tid + i * 256;      // 0..511
            int k = idx >> 5;             // 0..15
            int n4 = (idx & 31) * 4;
            *(float4*)&Ws[k][n4] = *(const float4*)(W + (long)(kt + k) * 128 + n4);
        }
        __syncthreads();
#pragma unroll
        for (int k = 0; k < 16; k++) {
            float a[8], b[8];
            *(float4*)(a)     = *(float4*)&As[k][m0];
            *(float4*)(a + 4) = *(float4*)&As[k][m0 + 4];
            *(float4*)(b)     = *(float4*)&Ws[k][n0];
            *(float4*)(b + 4) = *(float4*)&Ws[k][n0 + 4];
#pragma unroll
            for (int i = 0; i < 8; i++)
#pragma unroll
                for (int j = 0; j < 8; j++)
                    acc[i][j] = fmaf(a[i], b[j], acc[i][j]);
        }
        __syncthreads();
    }
    // Epilogue: scale by dinv[row]
#pragma unroll
    for (int i = 0; i < 8; i++) {
        int m = row0 + m0 + i;
        if (m < M) {
            float s = g_deg[m];
#pragma unroll
            for (int j = 0; j < 8; j += 4) {
                float4 v = make_float4(acc[i][j] * s, acc[i][j + 1] * s,
                                       acc[i][j + 2] * s, acc[i][j + 3] * s);
                *(float4*)(g_bufA + (long)m * 128 + n0 + j) = v;
            }
        }
    }
}

// ---------------- copy (self-loop init): bufB = bufA ----------------
__global__ void k_copy(int n_f4) {
    int stride = gridDim.x * blockDim.x;
    const float4* src = (const float4*)g_bufA;
    float4* dst = (float4*)g_bufB;
    for (int i = blockIdx.x * blockDim.x + threadIdx.x; i < n_f4; i += stride)
        dst[i] = src[i];
}

// ---------------- edge scatter: bufB[dst] += bufA[src] ----------------
__global__ void k_edges(const int* __restrict__ ei, int e) {
    int gwarp = (blockIdx.x * blockDim.x + threadIdx.x) >> 5;
    int lane = threadIdx.x & 31;
    int nwarp = (gridDim.x * blockDim.x) >> 5;
    const float* __restrict__ src_h = g_bufA;
    float* __restrict__ dst_h = g_bufB;
    for (int idx = gwarp; idx < e; idx += nwarp) {
        int s = ei[idx];
        int d = ei[e + idx];
        if ((unsigned)s >= NN || (unsigned)d >= NN) continue;
        float4 v = *(const float4*)(src_h + (long)s * 128 + lane * 4);
        float* dp = dst_h + (long)d * 128 + lane * 4;
        atomicAdd(dp + 0, v.x);
        atomicAdd(dp + 1, v.y);
        atomicAdd(dp + 2, v.z);
        atomicAdd(dp + 3, v.w);
    }
}

// ---------------- post: bufB = relu(dinv[n]*bufB + b) ----------------
__global__ void k_post(const float* __restrict__ bias, int n) {
    int stride = gridDim.x * blockDim.x;
    int total = n * 32;  // float4 count
    float4* h = (float4*)g_bufB;
    for (int i = blockIdx.x * blockDim.x + threadIdx.x; i < total; i += stride) {
        int node = i >> 5;
        int f4 = (i & 31) * 4;
        float s = g_deg[node];
        float4 v = h[i];
        float4 b = *(const float4*)(bias + f4);
        v.x = fmaxf(fmaf(s, v.x, b.x), 0.f);
        v.y = fmaxf(fmaf(s, v.y, b.y), 0.f);
        v.z = fmaxf(fmaf(s, v.z, b.z), 0.f);
        v.w = fmaxf(fmaf(s, v.w, b.w), 0.f);
        h[i] = v;
    }
}

// ---------------- pooling ----------------
__global__ void k_pool_init() {
    int i = blockIdx.x * blockDim.x + threadIdx.x;
    if (i < NG * FD) g_pool[i] = 0.f;
    if (i < NG) g_cnt[i] = 0.f;
}

// blockDim = 128 (one thread per feature); exploits sorted batch for
// register accumulation, flushing only on graph-id change.
__global__ void k_pool(const int* __restrict__ batch, int n) {
    int f = threadIdx.x;
    int npb = (n + gridDim.x - 1) / gridDim.x;
    int n0 = blockIdx.x * npb;
    int n1 = min(n0 + npb, n);
    if (n0 >= n1) return;
    float acc = 0.f, cnt = 0.f;
    int cg = batch[n0];
    for (int node = n0; node < n1; node++) {
        int g = batch[node];
        if (g != cg) {
            if ((unsigned)cg < NG) {
                atomicAdd(&g_pool[cg * FD + f], acc);
                if (f == 0) atomicAdd(&g_cnt[cg], cnt);
            }
            acc = 0.f; cnt = 0.f; cg = g;
        }
        acc += g_bufB[(long)node * 128 + f];
        cnt += 1.f;
    }
    if ((unsigned)cg < NG) {
        atomicAdd(&g_pool[cg * FD + f], acc);
        if (f == 0) atomicAdd(&g_cnt[cg], cnt);
    }
}

// ---------------- final linear: out[g][o] = (pool[g]/cnt)@wc + bc ----------------
__global__ void k_final(const float* __restrict__ wc, const float* __restrict__ bc,
                        float* __restrict__ out) {
    int g = blockIdx.x;
    int o = threadIdx.x;
    if (o >= OD) return;
    float inv = 1.f / fmaxf(g_cnt[g], 1.f);
    float s = 0.f;
#pragma unroll 8
    for (int f = 0; f < FD; f++)
        s = fmaf(g_pool[g * FD + f], wc[f * OD + o], s);
    out[g * OD + o] = s * inv + bc[o];
}

extern "C" void kernel_launch(void* const* d_in, const int* in_sizes, int n_in,
                              void* d_out, int out_size) {
    const float* x     = (const float*)d_in[0];
    const int*   ei    = (const int*)d_in[1];     // [2,E] (int64 normalized to int32)
    const int*   batch = (const int*)d_in[2];     // [N]
    const float* w1    = (const float*)d_in[3];
    const float* b1    = (const float*)d_in[4];
    const float* w2    = (const float*)d_in[5];
    const float* b2    = (const float*)d_in[6];
    const float* wc    = (const float*)d_in[7];
    const float* bc    = (const float*)d_in[8];
    float* out = (float*)d_out;

    int n = in_sizes[0] / FD;      // 100000
    int e = in_sizes[1] / 2;       // 1600000

    int n_f4 = n * 32;
    int gemm_blocks = (n + 127) / 128;

    // degree / dinv
    k_deg_init<<<(n + 255) / 256, 256>>>(n);
    k_deg_count<<<1024, 256>>>(ei, e);
    k_dinv<<<(n + 255) / 256, 256>>>(n);

    // layer 1
    k_gemm_dinv<<<gemm_blocks, 256>>>(x, w1, n, 0);
    k_copy<<<2048, 256>>>(n_f4);
    k_edges<<<2048, 256>>>(ei, e);
    k_post<<<2048, 256>>>(b1, n);

    // layer 2
    k_gemm_dinv<<<gemm_blocks, 256>>>(x, w2, n, 1);
    k_copy<<<2048, 256>>>(n_f4);
    k_edges<<<2048, 256>>>(ei, e);
    k_post<<<2048, 256>>>(b2, n);

    // pool + head
    k_pool_init<<<(NG * FD + 255) / 256, 256>>>();
    k_pool<<<512, 128>>>(batch, n);
    k_final<<<NG, 32>>>(wc, bc, out);
}

// round 4
// speedup vs baseline: 2.1434x; 2.1434x over previous
#include <cuda_runtime.h>
#include <cuda_bf16.h>

#define NN 100000
#define EE 1600000
#define FD 128
#define NG 128
#define OD 16

// Scratch (device globals — no allocs allowed)
__device__ float g_deg[NN];               // dinv = rsqrt(indeg+1)
__device__ int   g_cnt_i[NN];             // in-degree counts
__device__ int   g_off[NN + 1];           // CSR row offsets
__device__ int   g_pos[NN];               // scatter cursors
__device__ int   g_csr_src[EE];           // src ids grouped by dst
__device__ float g_bufA[(long)NN * FD];   // GEMM output (scaled by dinv[src])
__device__ float g_bufB[(long)NN * FD];   // aggregated layer output
__device__ float g_pool[NG * FD];
__device__ float g_cnt[NG];

// ---------------- CSR build ----------------
__global__ void k_count_init(int n) {
    int i = blockIdx.x * blockDim.x + threadIdx.x;
    if (i < n) g_cnt_i[i] = 0;
}

__global__ void k_count(const int* __restrict__ ei, int e) {
    int stride = gridDim.x * blockDim.x;
    for (int i = blockIdx.x * blockDim.x + threadIdx.x; i < e; i += stride) {
        int d = ei[e + i];
        if ((unsigned)d < NN) atomicAdd(&g_cnt_i[d], 1);
    }
}

// Single block, 1024 threads: exclusive scan of counts -> g_off/g_pos,
// plus dinv = rsqrt(count+1).
__global__ __launch_bounds__(1024) void k_scan(int n) {
    __shared__ int part[1024];
    int t = threadIdx.x;
    int chunk = (n + 1023) / 1024;
    int lo = t * chunk, hi = min(lo + chunk, n);
    int s = 0;
    for (int i = lo; i < hi; i++) s += g_cnt_i[i];
    part[t] = s;
    __syncthreads();
    for (int off = 1; off < 1024; off <<= 1) {
        int tmp = (t >= off) ? part[t - off] : 0;
        __syncthreads();
        part[t] += tmp;
        __syncthreads();
    }
    int run = part[t] - s;  // exclusive base
    for (int i = lo; i < hi; i++) {
        int c = g_cnt_i[i];
        g_off[i] = run;
        g_pos[i] = run;
        g_deg[i] = rsqrtf((float)(c + 1));
        run += c;
    }
    if (t == 1023) g_off[n] = part[1023];
}

__global__ void k_scatter(const int* __restrict__ ei, int e) {
    int stride = gridDim.x * blockDim.x;
    for (int i = blockIdx.x * blockDim.x + threadIdx.x; i < e; i += stride) {
        int s = ei[i];
        int d = ei[e + i];
        if ((unsigned)s >= NN || (unsigned)d >= NN) continue;
        int p = atomicAdd(&g_pos[d], 1);
        g_csr_src[p] = s;
    }
}

// ---------------- GEMM: g_bufA[m][:] = (A[m][:] @ W) * dinv[m] ----------------
__global__ __launch_bounds__(256) void k_gemm_dinv(
    const float* __restrict__ Ax, const float* __restrict__ W,
    int M, int src_sel)
{
    const float* __restrict__ A = src_sel ? (const float*)g_bufB : Ax;
    __shared__ float As[16][128];
    __shared__ float Ws[16][128];
    const int tid = threadIdx.x;
    const int row0 = blockIdx.x * 128;
    const int ty = tid >> 4, tx = tid & 15;
    const int m0 = ty * 8, n0 = tx * 8;
    const int lm = tid & 127;

    float acc[8][8];
#pragma unroll
    for (int i = 0; i < 8; i++)
#pragma unroll
        for (int j = 0; j < 8; j++) acc[i][j] = 0.f;

    for (int kt = 0; kt < 128; kt += 16) {
        int mA = row0 + lm;
#pragma unroll
        for (int i = 0; i < 2; i++) {
            int q = ((tid >> 7) << 1) + i;
            float4 v = make_float4(0.f, 0.f, 0.f, 0.f);
            if (mA < M) v = *(const float4*)(A + (long)mA * 128 + kt + q * 4);
            As[q * 4 + 0][lm] = v.x;
            As[q * 4 + 1][lm] = v.y;
            As[q * 4 + 2][lm] = v.z;
            As[q * 4 + 3][lm] = v.w;
        }
#pragma unroll
        for (int i = 0; i < 2; i++) {
            int idx = tid + i * 256;
            int k = idx >> 5;
            int n4 = (idx & 31) * 4;
            *(float4*)&Ws[k][n4] = *(const float4*)(W + (long)(kt + k) * 128 + n4);
        }
        __syncthreads();
#pragma unroll
        for (int k = 0; k < 16; k++) {
            float a[8], b[8];
            *(float4*)(a)     = *(float4*)&As[k][m0];
            *(float4*)(a + 4) = *(float4*)&As[k][m0 + 4];
            *(float4*)(b)     = *(float4*)&Ws[k][n0];
            *(float4*)(b + 4) = *(float4*)&Ws[k][n0 + 4];
#pragma unroll
            for (int i = 0; i < 8; i++)
#pragma unroll
                for (int j = 0; j < 8; j++)
                    acc[i][j] = fmaf(a[i], b[j], acc[i][j]);
        }
        __syncthreads();
    }
#pragma unroll
    for (int i = 0; i < 8; i++) {
        int m = row0 + m0 + i;
        if (m < M) {
            float s = g_deg[m];
#pragma unroll
            for (int j = 0; j < 8; j += 4) {
                float4 v = make_float4(acc[i][j] * s, acc[i][j + 1] * s,
                                       acc[i][j + 2] * s, acc[i][j + 3] * s);
                *(float4*)(g_bufA + (long)m * 128 + n0 + j) = v;
            }
        }
    }
}

// ---------------- pull aggregation (fused self-loop + dinv + bias + relu) ----
// one warp per dst node; lane owns 4 features (float4).
__global__ __launch_bounds__(256) void k_aggregate(const float* __restrict__ bias, int n) {
    int w = (blockIdx.x * blockDim.x + threadIdx.x) >> 5;
    int lane = threadIdx.x & 31;
    int nw = (gridDim.x * blockDim.x) >> 5;
    float4 b = *(const float4*)(bias + lane * 4);
    for (int d = w; d < n; d += nw) {
        float4 acc = *(const float4*)(g_bufA + (long)d * 128 + lane * 4);  // self-loop
        int lo = g_off[d], hi = g_off[d + 1];
        int j = lo;
        for (; j + 3 < hi; j += 4) {
            int s0 = g_csr_src[j], s1 = g_csr_src[j + 1];
            int s2 = g_csr_src[j + 2], s3 = g_csr_src[j + 3];
            float4 v0 = *(const float4*)(g_bufA + (long)s0 * 128 + lane * 4);
            float4 v1 = *(const float4*)(g_bufA + (long)s1 * 128 + lane * 4);
            float4 v2 = *(const float4*)(g_bufA + (long)s2 * 128 + lane * 4);
            float4 v3 = *(const float4*)(g_bufA + (long)s3 * 128 + lane * 4);
            acc.x += v0.x + v1.x + v2.x + v3.x;
            acc.y += v0.y + v1.y + v2.y + v3.y;
            acc.z += v0.z + v1.z + v2.z + v3.z;
            acc.w += v0.w + v1.w + v2.w + v3.w;
        }
        for (; j < hi; j++) {
            int s = g_csr_src[j];
            float4 v = *(const float4*)(g_bufA + (long)s * 128 + lane * 4);
            acc.x += v.x; acc.y += v.y; acc.z += v.z; acc.w += v.w;
        }
        float sc = g_deg[d];
        float4 o;
        o.x = fmaxf(fmaf(sc, acc.x, b.x), 0.f);
        o.y = fmaxf(fmaf(sc, acc.y, b.y), 0.f);
        o.z = fmaxf(fmaf(sc, acc.z, b.z), 0.f);
        o.w = fmaxf(fmaf(sc, acc.w, b.w), 0.f);
        *(float4*)(g_bufB + (long)d * 128 + lane * 4) = o;
    }
}

// ---------------- pooling ----------------
__global__ void k_pool_init() {
    int i = blockIdx.x * blockDim.x + threadIdx.x;
    if (i < NG * FD) g_pool[i] = 0.f;
    if (i < NG) g_cnt[i] = 0.f;
}

// warp per node-range; lane owns 4 features; flush on graph change (batch sorted).
__global__ __launch_bounds__(256) void k_pool(const int* __restrict__ batch, int n) {
    int w = (blockIdx.x * blockDim.x + threadIdx.x) >> 5;
    int lane = threadIdx.x & 31;
    int nw = (gridDim.x * blockDim.x) >> 5;
    int npb = (n + nw - 1) / nw;
    int n0 = w * npb;
    int n1 = min(n0 + npb, n);
    if (n0 >= n1) return;
    float4 acc = make_float4(0.f, 0.f, 0.f, 0.f);
    float cnt = 0.f;
    int cg = batch[n0];
    for (int node = n0; node < n1; node++) {
        int g = batch[node];
        if (g != cg) {
            if ((unsigned)cg < NG) {
                float* p = g_pool + cg * FD + lane * 4;
                atomicAdd(p + 0, acc.x); atomicAdd(p + 1, acc.y);
                atomicAdd(p + 2, acc.z); atomicAdd(p + 3, acc.w);
                if (lane == 0) atomicAdd(&g_cnt[cg], cnt);
            }
            acc = make_float4(0.f, 0.f, 0.f, 0.f); cnt = 0.f; cg = g;
        }
        float4 v = *(const float4*)(g_bufB + (long)node * 128 + lane * 4);
        acc.x += v.x; acc.y += v.y; acc.z += v.z; acc.w += v.w;
        cnt += 1.f;
    }
    if ((unsigned)cg < NG) {
        float* p = g_pool + cg * FD + lane * 4;
        atomicAdd(p + 0, acc.x); atomicAdd(p + 1, acc.y);
        atomicAdd(p + 2, acc.z); atomicAdd(p + 3, acc.w);
        if (lane == 0) atomicAdd(&g_cnt[cg], cnt);
    }
}

// ---------------- final linear ----------------
__global__ void k_final(const float* __restrict__ wc, const float* __restrict__ bc,
                        float* __restrict__ out) {
    int g = blockIdx.x;
    int o = threadIdx.x;
    if (o >= OD) return;
    float inv = 1.f / fmaxf(g_cnt[g], 1.f);
    float s = 0.f;
#pragma unroll 8
    for (int f = 0; f < FD; f++)
        s = fmaf(g_pool[g * FD + f], wc[f * OD + o], s);
    out[g * OD + o] = s * inv + bc[o];
}

extern "C" void kernel_launch(void* const* d_in, const int* in_sizes, int n_in,
                              void* d_out, int out_size) {
    const float* x     = (const float*)d_in[0];
    const int*   ei    = (const int*)d_in[1];
    const int*   batch = (const int*)d_in[2];
    const float* w1    = (const float*)d_in[3];
    const float* b1    = (const float*)d_in[4];
    const float* w2    = (const float*)d_in[5];
    const float* b2    = (const float*)d_in[6];
    const float* wc    = (const float*)d_in[7];
    const float* bc    = (const float*)d_in[8];
    float* out = (float*)d_out;

    int n = in_sizes[0] / FD;      // 100000
    int e = in_sizes[1] / 2;       // 1600000
    int gemm_blocks = (n + 127) / 128;

    // CSR build (also produces dinv)
    k_count_init<<<(n + 255) / 256, 256>>>(n);
    k_count<<<1024, 256>>>(ei, e);
    k_scan<<<1, 1024>>>(n);
    k_scatter<<<1024, 256>>>(ei, e);

    // layer 1
    k_gemm_dinv<<<gemm_blocks, 256>>>(x, w1, n, 0);
    k_aggregate<<<4096, 256>>>(b1, n);

    // layer 2
    k_gemm_dinv<<<gemm_blocks, 256>>>(x, w2, n, 1);
    k_aggregate<<<4096, 256>>>(b2, n);

    // pool + head
    k_pool_init<<<(NG * FD + 255) / 256, 256>>>();
    k_pool<<<2048, 256>>>(batch, n);
    k_final<<<NG, 32>>>(wc, bc, out);
}

// round 5
// speedup vs baseline: 2.1807x; 1.0174x over previous
#include <cuda_runtime.h>
#include <cuda_bf16.h>

#define NN 100000
#define EE 1600000
#define FD 128
#define NG 128
#define OD 16

// Scratch (device globals — no allocs allowed)
__device__ float g_deg[NN];               // dinv = rsqrt(indeg+1)
__device__ int   g_cnt_i[NN];             // in-degree counts
__device__ int   g_off[NN + 1];           // CSR row offsets
__device__ int   g_pos[NN];               // scatter cursors
__device__ int   g_csr_src[EE];           // src ids grouped by dst
__device__ float g_bufA[(long)NN * FD];   // GEMM output (unscaled)
__device__ float g_bufB[(long)NN * FD];   // layer-1 output
__device__ float g_pool[NG * FD];
__device__ float g_cnt[NG];

// ---------------- CSR build ----------------
__global__ void k_count_init(int n) {
    int i = blockIdx.x * blockDim.x + threadIdx.x;
    if (i < n) g_cnt_i[i] = 0;
}

__global__ void k_count(const int* __restrict__ ei, int e) {
    int stride = gridDim.x * blockDim.x;
    for (int i = blockIdx.x * blockDim.x + threadIdx.x; i < e; i += stride) {
        int d = ei[e + i];
        if ((unsigned)d < NN) atomicAdd(&g_cnt_i[d], 1);
    }
}

__global__ __launch_bounds__(1024) void k_scan(int n) {
    __shared__ int part[1024];
    int t = threadIdx.x;
    int chunk = (n + 1023) / 1024;
    int lo = t * chunk, hi = min(lo + chunk, n);
    int s = 0;
    for (int i = lo; i < hi; i++) s += g_cnt_i[i];
    part[t] = s;
    __syncthreads();
    for (int off = 1; off < 1024; off <<= 1) {
        int tmp = (t >= off) ? part[t - off] : 0;
        __syncthreads();
        part[t] += tmp;
        __syncthreads();
    }
    int run = part[t] - s;  // exclusive base
    for (int i = lo; i < hi; i++) {
        int c = g_cnt_i[i];
        g_off[i] = run;
        g_pos[i] = run;
        g_deg[i] = rsqrtf((float)(c + 1));
        run += c;
    }
    if (t == 1023) g_off[n] = part[1023];
}

__global__ void k_scatter(const int* __restrict__ ei, int e) {
    int stride = gridDim.x * blockDim.x;
    for (int i = blockIdx.x * blockDim.x + threadIdx.x; i < e; i += stride) {
        int s = ei[i];
        int d = ei[e + i];
        if ((unsigned)s >= NN || (unsigned)d >= NN) continue;
        int p = atomicAdd(&g_pos[d], 1);
        g_csr_src[p] = s;
    }
}

__global__ void k_pool_init() {
    int i = blockIdx.x * blockDim.x + threadIdx.x;
    if (i < NG * FD) g_pool[i] = 0.f;
    if (i < NG) g_cnt[i] = 0.f;
}

// ---------------- GEMM: g_bufA = A @ W (no scaling) ----------------
__global__ __launch_bounds__(256) void k_gemm(
    const float* __restrict__ Ax, const float* __restrict__ W,
    int M, int src_sel)
{
    const float* __restrict__ A = src_sel ? (const float*)g_bufB : Ax;
    __shared__ float As[16][128];
    __shared__ float Ws[16][128];
    const int tid = threadIdx.x;
    const int row0 = blockIdx.x * 128;
    const int ty = tid >> 4, tx = tid & 15;
    const int m0 = ty * 8, n0 = tx * 8;
    const int lm = tid & 127;

    float acc[8][8];
#pragma unroll
    for (int i = 0; i < 8; i++)
#pragma unroll
        for (int j = 0; j < 8; j++) acc[i][j] = 0.f;

    for (int kt = 0; kt < 128; kt += 16) {
        int mA = row0 + lm;
#pragma unroll
        for (int i = 0; i < 2; i++) {
            int q = ((tid >> 7) << 1) + i;
            float4 v = make_float4(0.f, 0.f, 0.f, 0.f);
            if (mA < M) v = *(const float4*)(A + (long)mA * 128 + kt + q * 4);
            As[q * 4 + 0][lm] = v.x;
            As[q * 4 + 1][lm] = v.y;
            As[q * 4 + 2][lm] = v.z;
            As[q * 4 + 3][lm] = v.w;
        }
#pragma unroll
        for (int i = 0; i < 2; i++) {
            int idx = tid + i * 256;
            int k = idx >> 5;
            int n4 = (idx & 31) * 4;
            *(float4*)&Ws[k][n4] = *(const float4*)(W + (long)(kt + k) * 128 + n4);
        }
        __syncthreads();
#pragma unroll
        for (int k = 0; k < 16; k++) {
            float a[8], b[8];
            *(float4*)(a)     = *(float4*)&As[k][m0];
            *(float4*)(a + 4) = *(float4*)&As[k][m0 + 4];
            *(float4*)(b)     = *(float4*)&Ws[k][n0];
            *(float4*)(b + 4) = *(float4*)&Ws[k][n0 + 4];
#pragma unroll
            for (int i = 0; i < 8; i++)
#pragma unroll
                for (int j = 0; j < 8; j++)
                    acc[i][j] = fmaf(a[i], b[j], acc[i][j]);
        }
        __syncthreads();
    }
#pragma unroll
    for (int i = 0; i < 8; i++) {
        int m = row0 + m0 + i;
        if (m < M) {
#pragma unroll
            for (int j = 0; j < 8; j += 4) {
                float4 v = make_float4(acc[i][j], acc[i][j + 1],
                                       acc[i][j + 2], acc[i][j + 3]);
                *(float4*)(g_bufA + (long)m * 128 + n0 + j) = v;
            }
        }
    }
}

// per-node body: acc = Σ_{s ∈ N(d) ∪ {d}} dinv[s] * bufA[s]  (lane's float4 slice)
__device__ __forceinline__ float4 node_gather(int d, int lane) {
    float dd = g_deg[d];
    float4 self = *(const float4*)(g_bufA + (long)d * 128 + lane * 4);
    float4 acc = make_float4(self.x * dd, self.y * dd, self.z * dd, self.w * dd);
    int lo = g_off[d], hi = g_off[d + 1];
    int j = lo;
    for (; j + 3 < hi; j += 4) {
        int s0 = g_csr_src[j], s1 = g_csr_src[j + 1];
        int s2 = g_csr_src[j + 2], s3 = g_csr_src[j + 3];
        float d0 = g_deg[s0], d1 = g_deg[s1], d2 = g_deg[s2], d3 = g_deg[s3];
        float4 v0 = *(const float4*)(g_bufA + (long)s0 * 128 + lane * 4);
        float4 v1 = *(const float4*)(g_bufA + (long)s1 * 128 + lane * 4);
        float4 v2 = *(const float4*)(g_bufA + (long)s2 * 128 + lane * 4);
        float4 v3 = *(const float4*)(g_bufA + (long)s3 * 128 + lane * 4);
        acc.x = fmaf(v0.x, d0, fmaf(v1.x, d1, fmaf(v2.x, d2, fmaf(v3.x, d3, acc.x))));
        acc.y = fmaf(v0.y, d0, fmaf(v1.y, d1, fmaf(v2.y, d2, fmaf(v3.y, d3, acc.y))));
        acc.z = fmaf(v0.z, d0, fmaf(v1.z, d1, fmaf(v2.z, d2, fmaf(v3.z, d3, acc.z))));
        acc.w = fmaf(v0.w, d0, fmaf(v1.w, d1, fmaf(v2.w, d2, fmaf(v3.w, d3, acc.w))));
    }
    for (; j < hi; j++) {
        int s = g_csr_src[j];
        float ds = g_deg[s];
        float4 v = *(const float4*)(g_bufA + (long)s * 128 + lane * 4);
        acc.x = fmaf(v.x, ds, acc.x);
        acc.y = fmaf(v.y, ds, acc.y);
        acc.z = fmaf(v.z, ds, acc.z);
        acc.w = fmaf(v.w, ds, acc.w);
    }
    return acc;
}

// ---------------- layer-1 aggregate: bufB = relu(dinv[d]*acc + b) ----------
__global__ __launch_bounds__(256) void k_aggregate(const float* __restrict__ bias, int n) {
    int w = (blockIdx.x * blockDim.x + threadIdx.x) >> 5;
    int lane = threadIdx.x & 31;
    int nw = (gridDim.x * blockDim.x) >> 5;
    float4 b = *(const float4*)(bias + lane * 4);
    for (int d = w; d < n; d += nw) {
        float4 acc = node_gather(d, lane);
        float sc = g_deg[d];
        float4 o;
        o.x = fmaxf(fmaf(sc, acc.x, b.x), 0.f);
        o.y = fmaxf(fmaf(sc, acc.y, b.y), 0.f);
        o.z = fmaxf(fmaf(sc, acc.z, b.z), 0.f);
        o.w = fmaxf(fmaf(sc, acc.w, b.w), 0.f);
        *(float4*)(g_bufB + (long)d * 128 + lane * 4) = o;
    }
}

// ---------------- layer-2 aggregate fused with mean-pool accumulation ------
// warp handles contiguous node range; batch sorted -> register pooled acc.
__global__ __launch_bounds__(256) void k_agg_pool(
    const float* __restrict__ bias, const int* __restrict__ batch, int n)
{
    int w = (blockIdx.x * blockDim.x + threadIdx.x) >> 5;
    int lane = threadIdx.x & 31;
    int nw = (gridDim.x * blockDim.x) >> 5;
    int npb = (n + nw - 1) / nw;
    int n0 = w * npb;
    int n1 = min(n0 + npb, n);
    if (n0 >= n1) return;
    float4 b = *(const float4*)(bias + lane * 4);
    float4 pacc = make_float4(0.f, 0.f, 0.f, 0.f);
    float cnt = 0.f;
    int cg = batch[n0];
    for (int d = n0; d < n1; d++) {
        int g = batch[d];
        if (g != cg) {
            if ((unsigned)cg < NG) {
                float* p = g_pool + cg * FD + lane * 4;
                atomicAdd(p + 0, pacc.x); atomicAdd(p + 1, pacc.y);
                atomicAdd(p + 2, pacc.z); atomicAdd(p + 3, pacc.w);
                if (lane == 0) atomicAdd(&g_cnt[cg], cnt);
            }
            pacc = make_float4(0.f, 0.f, 0.f, 0.f); cnt = 0.f; cg = g;
        }
        float4 acc = node_gather(d, lane);
        float sc = g_deg[d];
        pacc.x += fmaxf(fmaf(sc, acc.x, b.x), 0.f);
        pacc.y += fmaxf(fmaf(sc, acc.y, b.y), 0.f);
        pacc.z += fmaxf(fmaf(sc, acc.z, b.z), 0.f);
        pacc.w += fmaxf(fmaf(sc, acc.w, b.w), 0.f);
        cnt += 1.f;
    }
    if ((unsigned)cg < NG) {
        float* p = g_pool + cg * FD + lane * 4;
        atomicAdd(p + 0, pacc.x); atomicAdd(p + 1, pacc.y);
        atomicAdd(p + 2, pacc.z); atomicAdd(p + 3, pacc.w);
        if (lane == 0) atomicAdd(&g_cnt[cg], cnt);
    }
}

// ---------------- final linear ----------------
__global__ void k_final(const float* __restrict__ wc, const float* __restrict__ bc,
                        float* __restrict__ out) {
    int g = blockIdx.x;
    int o = threadIdx.x;
    if (o >= OD) return;
    float inv = 1.f / fmaxf(g_cnt[g], 1.f);
    float s = 0.f;
#pragma unroll 8
    for (int f = 0; f < FD; f++)
        s = fmaf(g_pool[g * FD + f], wc[f * OD + o], s);
    out[g * OD + o] = s * inv + bc[o];
}

extern "C" void kernel_launch(void* const* d_in, const int* in_sizes, int n_in,
                              void* d_out, int out_size) {
    const float* x     = (const float*)d_in[0];
    const int*   ei    = (const int*)d_in[1];
    const int*   batch = (const int*)d_in[2];
    const float* w1    = (const float*)d_in[3];
    const float* b1    = (const float*)d_in[4];
    const float* w2    = (const float*)d_in[5];
    const float* b2    = (const float*)d_in[6];
    const float* wc    = (const float*)d_in[7];
    const float* bc    = (const float*)d_in[8];
    float* out = (float*)d_out;

    int n = in_sizes[0] / FD;      // 100000
    int e = in_sizes[1] / 2;       // 1600000
    int gemm_blocks = (n + 127) / 128;

    // lazily-created side stream + events (host objects; no device allocs)
    static cudaStream_t s_side = nullptr;
    static cudaEvent_t ev_fork = nullptr, ev_join = nullptr;
    if (!s_side) {
        cudaStreamCreateWithFlags(&s_side, cudaStreamNonBlocking);
        cudaEventCreateWithFlags(&ev_fork, cudaEventDisableTiming);
        cudaEventCreateWithFlags(&ev_join, cudaEventDisableTiming);
    }

    // fork: CSR build + pool init on side stream, GEMM1 on main stream
    cudaEventRecord(ev_fork, 0);
    cudaStreamWaitEvent(s_side, ev_fork, 0);
    k_count_init<<<(n + 255) / 256, 256, 0, s_side>>>(n);
    k_count<<<1024, 256, 0, s_side>>>(ei, e);
    k_scan<<<1, 1024, 0, s_side>>>(n);
    k_scatter<<<1024, 256, 0, s_side>>>(ei, e);
    k_pool_init<<<(NG * FD + 255) / 256, 256, 0, s_side>>>();
    cudaEventRecord(ev_join, s_side);

    k_gemm<<<gemm_blocks, 256>>>(x, w1, n, 0);
    cudaStreamWaitEvent(0, ev_join, 0);

    // layer 1
    k_aggregate<<<4096, 256>>>(b1, n);
    // layer 2 (aggregate fused with pooling)
    k_gemm<<<gemm_blocks, 256>>>(x, w2, n, 1);
    k_agg_pool<<<2048, 256>>>(b2, batch, n);

    k_final<<<NG, 32>>>(wc, bc, out);
}